// round 1
// baseline (speedup 1.0000x reference)
#include <cuda_runtime.h>
#include <math.h>

#define NMAX 100000
#define DIM 128
#define LN_EPS 1e-5f

// ---------------- static scratch (no allocations allowed) ----------------
__device__ float g_deg [NMAX];
__device__ float g_dinv[NMAX];
__device__ float g_bufA[(size_t)NMAX * DIM];   // z (gemm out, pre-scaled by dinv[src])
__device__ float g_bufB[(size_t)NMAX * DIM];   // acc (scatter target)
__device__ float g_bufC[(size_t)NMAX * DIM];   // h (layer activations)

// ---------------- degree / dinv ----------------
__global__ void deg_init_kernel(float* __restrict__ deg, int n) {
    int i = blockIdx.x * blockDim.x + threadIdx.x;
    if (i < n) deg[i] = 1.0f;  // self loop
}

__global__ void deg_count_kernel(const int* __restrict__ dst, float* __restrict__ deg, int E) {
    int e = blockIdx.x * blockDim.x + threadIdx.x;
    if (e < E) atomicAdd(&deg[dst[e]], 1.0f);
}

__global__ void dinv_kernel(const float* __restrict__ deg, float* __restrict__ dinv, int n) {
    int i = blockIdx.x * blockDim.x + threadIdx.x;
    if (i < n) dinv[i] = rsqrtf(fmaxf(deg[i], 1e-12f));
}

// ---------------- GEMM: out = A[M,128] @ W[128,NC] (+ epilogues) ----------------
// MODE 0: v *= dinv[row]; write v to out1 (z) AND out2 (acc seed = self loop)
// MODE 1: v += bias[c];   write out1
// MODE 2: v = sigmoid(v + bias[c]); write out1
template <int NC, int MODE>
__global__ void gemm_kernel(const float* __restrict__ A, const float* __restrict__ W,
                            const float* __restrict__ bias, const float* __restrict__ dinv,
                            float* __restrict__ out1, float* __restrict__ out2, int M) {
    extern __shared__ float smem[];
    float* sW = smem;                  // 128 * NC
    float* sA = smem + 128 * NC;       // 64 * 129 (padded stride: avoid bank conflicts)
    const int ROWS = 64;
    const int tid = threadIdx.x;       // 256 threads
    const int rowbase = blockIdx.x * ROWS;

    // load W (128 x NC) vectorized
    {
        const float4* Wv = (const float4*)W;
        float4* sWv = (float4*)sW;
        const int total = 128 * NC / 4;
        for (int i = tid; i < total; i += 256) sWv[i] = Wv[i];
    }
    // load A tile (ROWS x 128) with padded stride 129
    {
        const int nrows = min(ROWS, M - rowbase);
        for (int i = tid; i < ROWS * 32; i += 256) {
            int r = i >> 5, c = i & 31;
            float4 v = make_float4(0.f, 0.f, 0.f, 0.f);
            if (r < nrows)
                v = ((const float4*)(A + (size_t)(rowbase + r) * 128))[c];
            float* d = &sA[r * 129 + c * 4];
            d[0] = v.x; d[1] = v.y; d[2] = v.z; d[3] = v.w;
        }
    }
    __syncthreads();

    const int CPT = NC / 4;            // cols per thread
    const int r  = tid >> 2;           // local row (0..63)
    const int cb = (tid & 3) * CPT;    // col base

    float acc[CPT];
#pragma unroll
    for (int j = 0; j < CPT; j++) acc[j] = 0.f;

    const float4* sW4 = (const float4*)sW;
#pragma unroll 4
    for (int k = 0; k < 128; k++) {
        float a = sA[r * 129 + k];
#pragma unroll
        for (int j = 0; j < CPT / 4; j++) {
            float4 w = sW4[k * (NC / 4) + (cb >> 2) + j];
            acc[4 * j + 0] = fmaf(a, w.x, acc[4 * j + 0]);
            acc[4 * j + 1] = fmaf(a, w.y, acc[4 * j + 1]);
            acc[4 * j + 2] = fmaf(a, w.z, acc[4 * j + 2]);
            acc[4 * j + 3] = fmaf(a, w.w, acc[4 * j + 3]);
        }
    }

    const int grow = rowbase + r;
    if (grow >= M) return;

    if (MODE == 0) {
        const float s = dinv[grow];
        float4* o1 = (float4*)(out1 + (size_t)grow * NC + cb);
        float4* o2 = (float4*)(out2 + (size_t)grow * NC + cb);
#pragma unroll
        for (int j = 0; j < CPT / 4; j++) {
            float4 v = make_float4(acc[4*j] * s, acc[4*j+1] * s, acc[4*j+2] * s, acc[4*j+3] * s);
            o1[j] = v;
            o2[j] = v;
        }
    } else if (MODE == 1) {
        float4* o1 = (float4*)(out1 + (size_t)grow * NC + cb);
#pragma unroll
        for (int j = 0; j < CPT / 4; j++) {
            o1[j] = make_float4(acc[4*j]   + bias[cb + 4*j],
                                acc[4*j+1] + bias[cb + 4*j + 1],
                                acc[4*j+2] + bias[cb + 4*j + 2],
                                acc[4*j+3] + bias[cb + 4*j + 3]);
        }
    } else {
        float4* o1 = (float4*)(out1 + (size_t)grow * NC + cb);
#pragma unroll
        for (int j = 0; j < CPT / 4; j++) {
            float v0 = acc[4*j]   + bias[cb + 4*j];
            float v1 = acc[4*j+1] + bias[cb + 4*j + 1];
            float v2 = acc[4*j+2] + bias[cb + 4*j + 2];
            float v3 = acc[4*j+3] + bias[cb + 4*j + 3];
            o1[j] = make_float4(1.f / (1.f + expf(-v0)), 1.f / (1.f + expf(-v1)),
                                1.f / (1.f + expf(-v2)), 1.f / (1.f + expf(-v3)));
        }
    }
}

// ---------------- edge scatter: acc[dst] += z[src] (one warp per edge, float4 atomics) ----------------
__global__ void scatter_kernel(const int* __restrict__ src, const int* __restrict__ dst,
                               const float4* __restrict__ z4, float4* __restrict__ acc4, int E) {
    int gtid = blockIdx.x * blockDim.x + threadIdx.x;
    int warp = gtid >> 5;
    int lane = gtid & 31;
    if (warp >= E) return;
    int s = __ldg(&src[warp]);
    int d = __ldg(&dst[warp]);
    float4 v = __ldg(&z4[(size_t)s * 32 + lane]);
    atomicAdd(&acc4[(size_t)d * 32 + lane], v);   // sm_90+: native float4 RED
}

// ---------------- epilogue: h = post(dinv[row]*acc + b), post = ReLU (+ LayerNorm) ----------------
template <int DO_LN>
__global__ void epilogue_kernel(const float* __restrict__ acc, const float* __restrict__ dinv,
                                const float* __restrict__ b, const float* __restrict__ g,
                                const float* __restrict__ be, float* __restrict__ hout) {
    const int row = blockIdx.x;
    const int d = threadIdx.x;   // 128 threads
    float v = fmaf(dinv[row], acc[(size_t)row * 128 + d], b[d]);
    v = fmaxf(v, 0.f);
    if (DO_LN) {
        __shared__ float red[4];
        float s = v;
#pragma unroll
        for (int o = 16; o > 0; o >>= 1) s += __shfl_xor_sync(0xffffffffu, s, o);
        if ((d & 31) == 0) red[d >> 5] = s;
        __syncthreads();
        float mu = (red[0] + red[1] + red[2] + red[3]) * (1.f / 128.f);
        __syncthreads();
        float x = v - mu;
        float s2 = x * x;
#pragma unroll
        for (int o = 16; o > 0; o >>= 1) s2 += __shfl_xor_sync(0xffffffffu, s2, o);
        if ((d & 31) == 0) red[d >> 5] = s2;
        __syncthreads();
        float var = (red[0] + red[1] + red[2] + red[3]) * (1.f / 128.f);
        v = fmaf(g[d] * x, rsqrtf(var + LN_EPS), be[d]);
    }
    hout[(size_t)row * 128 + d] = v;
}

// ---------------- launch ----------------
extern "C" void kernel_launch(void* const* d_in, const int* in_sizes, int n_in,
                              void* d_out, int out_size) {
    const float* x   = (const float*)d_in[0];
    const int*   ei  = (const int*)  d_in[1];
    const float* W1  = (const float*)d_in[2];
    const float* b1  = (const float*)d_in[3];
    const float* W2  = (const float*)d_in[4];
    const float* b2  = (const float*)d_in[5];
    const float* W3  = (const float*)d_in[6];
    const float* b3  = (const float*)d_in[7];
    const float* g1  = (const float*)d_in[8];
    const float* be1 = (const float*)d_in[9];
    const float* g2  = (const float*)d_in[10];
    const float* be2 = (const float*)d_in[11];
    const float* Wp1 = (const float*)d_in[12];
    const float* bp1 = (const float*)d_in[13];
    const float* Wp2 = (const float*)d_in[14];
    const float* bp2 = (const float*)d_in[15];
    float* out = (float*)d_out;

    const int n = in_sizes[0] / DIM;          // 100000
    const int E = in_sizes[1] / 2;            // 1600000
    const int* src = ei;
    const int* dst = ei + E;

    float *deg, *dinv, *bufA, *bufB, *bufC;
    cudaGetSymbolAddress((void**)&deg,  g_deg);
    cudaGetSymbolAddress((void**)&dinv, g_dinv);
    cudaGetSymbolAddress((void**)&bufA, g_bufA);
    cudaGetSymbolAddress((void**)&bufB, g_bufB);
    cudaGetSymbolAddress((void**)&bufC, g_bufC);

    const int SMEM128 = (128 * 128 + 64 * 129) * 4;  // 98560 B
    const int SMEM64  = (128 * 64  + 64 * 129) * 4;  // 65792 B
    cudaFuncSetAttribute(gemm_kernel<128, 0>, cudaFuncAttributeMaxDynamicSharedMemorySize, SMEM128);
    cudaFuncSetAttribute(gemm_kernel<128, 1>, cudaFuncAttributeMaxDynamicSharedMemorySize, SMEM128);
    cudaFuncSetAttribute(gemm_kernel<64,  2>, cudaFuncAttributeMaxDynamicSharedMemorySize, SMEM64);

    const int gemm_grid = (n + 63) / 64;
    const int scat_grid = (E * 32 + 255) / 256;

    // degree / dinv
    deg_init_kernel<<<(n + 255) / 256, 256>>>(deg, n);
    deg_count_kernel<<<(E + 255) / 256, 256>>>(dst, deg, E);
    dinv_kernel<<<(n + 255) / 256, 256>>>(deg, dinv, n);

    // ---- conv1: x -> bufC (ReLU + LN) ----
    gemm_kernel<128, 0><<<gemm_grid, 256, SMEM128>>>(x, W1, nullptr, dinv, bufA, bufB, n);
    scatter_kernel<<<scat_grid, 256>>>(src, dst, (const float4*)bufA, (float4*)bufB, E);
    epilogue_kernel<1><<<n, 128>>>(bufB, dinv, b1, g1, be1, bufC);

    // ---- conv2: bufC -> bufC (ReLU + LN) ----
    gemm_kernel<128, 0><<<gemm_grid, 256, SMEM128>>>(bufC, W2, nullptr, dinv, bufA, bufB, n);
    scatter_kernel<<<scat_grid, 256>>>(src, dst, (const float4*)bufA, (float4*)bufB, E);
    epilogue_kernel<1><<<n, 128>>>(bufB, dinv, b2, g2, be2, bufC);

    // ---- conv3: bufC -> bufC (ReLU only) ----
    gemm_kernel<128, 0><<<gemm_grid, 256, SMEM128>>>(bufC, W3, nullptr, dinv, bufA, bufB, n);
    scatter_kernel<<<scat_grid, 256>>>(src, dst, (const float4*)bufA, (float4*)bufB, E);
    epilogue_kernel<0><<<n, 128>>>(bufB, dinv, b3, nullptr, nullptr, bufC);

    // ---- heads: Wp1 (+bias), Wp2 (+bias, sigmoid) -> out ----
    gemm_kernel<128, 1><<<gemm_grid, 256, SMEM128>>>(bufC, Wp1, bp1, nullptr, bufA, nullptr, n);
    gemm_kernel<64,  2><<<gemm_grid, 256, SMEM64 >>>(bufA, Wp2, bp2, nullptr, out,  nullptr, n);
}

// round 3
// speedup vs baseline: 2.7547x; 2.7547x over previous
#include <cuda_runtime.h>
#include <math.h>

#define NMAX 100000
#define DIM 128
#define LN_EPS 1e-5f

typedef unsigned long long u64;

// ---------------- packed f32x2 helpers (sm_103a) ----------------
#define FMA_F32X2(d, a, b) \
    asm("fma.rn.f32x2 %0, %1, %2, %0;" : "+l"(d) : "l"(a), "l"(b))
#define PACK_F32X2(out, lo, hi) \
    asm("mov.b64 %0, {%1, %2};" : "=l"(out) : "f"(lo), "f"(hi))
#define UNPACK_F32X2(lo, hi, in) \
    asm("mov.b64 {%0, %1}, %2;" : "=f"(lo), "=f"(hi) : "l"(in))

// ---------------- static scratch (no allocations allowed) ----------------
__device__ float g_deg [NMAX];
__device__ float g_dinv[NMAX];
__device__ float g_bufA[(size_t)NMAX * DIM];   // z (gemm out, pre-scaled by dinv[src])
__device__ float g_bufB[(size_t)NMAX * DIM];   // acc (scatter target, seeded with self-loop)
__device__ float g_bufC[(size_t)NMAX * DIM];   // h (layer activations)

// ---------------- degree / dinv ----------------
__global__ void deg_init_kernel(float* __restrict__ deg, int n) {
    int i = blockIdx.x * blockDim.x + threadIdx.x;
    if (i < n) deg[i] = 1.0f;  // self loop
}

__global__ void deg_count_kernel(const int* __restrict__ dst, float* __restrict__ deg, int E) {
    int e = blockIdx.x * blockDim.x + threadIdx.x;
    if (e < E) atomicAdd(&deg[dst[e]], 1.0f);
}

__global__ void dinv_kernel(const float* __restrict__ deg, float* __restrict__ dinv, int n) {
    int i = blockIdx.x * blockDim.x + threadIdx.x;
    if (i < n) dinv[i] = rsqrtf(fmaxf(deg[i], 1e-12f));
}

// ---------------- GEMM: out = A[M,128] @ W[128,BN] (+ epilogues) ----------------
// Register-blocked, packed f32x2 FMA. BM=64 rows/block, 256 threads,
// each thread: 4 rows x (BN/16) cols.
// MODE 0: v *= dinv[row]; write v to out1 (z) AND out2 (acc self-loop seed)
// MODE 1: v += bias[c];   write out1
// MODE 2: v = sigmoid(v + bias[c]); write out1
template <int BN, int MODE>
__global__ __launch_bounds__(256)
void gemm_kernel(const float* __restrict__ A, const float* __restrict__ W,
                 const float* __restrict__ bias, const float* __restrict__ dinv,
                 float* __restrict__ out1, float* __restrict__ out2, int M) {
    constexpr int BM = 64;
    constexpr int CPT = BN / 16;          // cols per thread (8 or 4)
    constexpr int NP  = CPT / 2;          // col-pairs per thread
    constexpr int SAS = BM + 4;           // sAT stride: pad 4 keeps 16B alignment for float4 loads

    extern __shared__ float smem[];
    float* sAT = smem;                    // [128][SAS]  A transposed: sAT[k][m]
    float* sW  = smem + 128 * SAS;        // [128][BN]   W row-major

    const int tid = threadIdx.x;
    const int cx = tid & 15;              // 0..15 col group
    const int tr = tid >> 4;              // 0..15 row group
    const int rowbase = blockIdx.x * BM;
    const int nrows = min(BM, M - rowbase);

    // load W (128 x BN), vectorized
    {
        const float4* Wv = (const float4*)W;
        float4* sWv = (float4*)sW;
        for (int i = tid; i < 128 * BN / 4; i += 256) sWv[i] = Wv[i];
    }
    // load A tile (64 x 128) transposed into sAT[k][m]
    for (int i = tid; i < BM * 32; i += 256) {
        int r = i >> 5, c4 = i & 31;
        float4 v = make_float4(0.f, 0.f, 0.f, 0.f);
        if (r < nrows)
            v = ((const float4*)(A + (size_t)(rowbase + r) * 128))[c4];
        sAT[(4 * c4 + 0) * SAS + r] = v.x;
        sAT[(4 * c4 + 1) * SAS + r] = v.y;
        sAT[(4 * c4 + 2) * SAS + r] = v.z;
        sAT[(4 * c4 + 3) * SAS + r] = v.w;
    }
    __syncthreads();

    const int r0 = tr * 4;                // local row base
    const int c0 = cx * CPT;              // col base

    u64 acc[4][NP];
#pragma unroll
    for (int i = 0; i < 4; i++)
#pragma unroll
        for (int j = 0; j < NP; j++) acc[i][j] = 0ULL;

#pragma unroll 8
    for (int k = 0; k < 128; k++) {
        float4 a4 = *(const float4*)&sAT[k * SAS + r0];     // 16B-aligned: SAS%4==0, r0%4==0
        u64 aa[4];
        PACK_F32X2(aa[0], a4.x, a4.x);
        PACK_F32X2(aa[1], a4.y, a4.y);
        PACK_F32X2(aa[2], a4.z, a4.z);
        PACK_F32X2(aa[3], a4.w, a4.w);
        const u64* w2 = (const u64*)&sW[k * BN + c0];       // c0%4==0 -> 16B aligned
        u64 wv[NP];
#pragma unroll
        for (int j = 0; j < NP; j++) wv[j] = w2[j];
#pragma unroll
        for (int j = 0; j < NP; j++) {
            FMA_F32X2(acc[0][j], aa[0], wv[j]);
            FMA_F32X2(acc[1][j], aa[1], wv[j]);
            FMA_F32X2(acc[2][j], aa[2], wv[j]);
            FMA_F32X2(acc[3][j], aa[3], wv[j]);
        }
    }

    // unpack + epilogue
    float bv[CPT];
    if (MODE != 0) {
#pragma unroll
        for (int j = 0; j < CPT; j++) bv[j] = __ldg(&bias[c0 + j]);
    }

#pragma unroll
    for (int i = 0; i < 4; i++) {
        const int grow = rowbase + r0 + i;
        if (grow >= M) break;
        float v[CPT];
#pragma unroll
        for (int j = 0; j < NP; j++) UNPACK_F32X2(v[2 * j], v[2 * j + 1], acc[i][j]);

        if (MODE == 0) {
            const float s = dinv[grow];
            float4* o1 = (float4*)(out1 + (size_t)grow * BN + c0);
            float4* o2 = (float4*)(out2 + (size_t)grow * BN + c0);
#pragma unroll
            for (int j = 0; j < CPT / 4; j++) {
                float4 o = make_float4(v[4*j] * s, v[4*j+1] * s, v[4*j+2] * s, v[4*j+3] * s);
                o1[j] = o;
                o2[j] = o;
            }
        } else if (MODE == 1) {
            float4* o1 = (float4*)(out1 + (size_t)grow * BN + c0);
#pragma unroll
            for (int j = 0; j < CPT / 4; j++)
                o1[j] = make_float4(v[4*j] + bv[4*j], v[4*j+1] + bv[4*j+1],
                                    v[4*j+2] + bv[4*j+2], v[4*j+3] + bv[4*j+3]);
        } else {
            float4* o1 = (float4*)(out1 + (size_t)grow * BN + c0);
#pragma unroll
            for (int j = 0; j < CPT / 4; j++) {
                float t0 = v[4*j]   + bv[4*j];
                float t1 = v[4*j+1] + bv[4*j+1];
                float t2 = v[4*j+2] + bv[4*j+2];
                float t3 = v[4*j+3] + bv[4*j+3];
                o1[j] = make_float4(1.f / (1.f + expf(-t0)), 1.f / (1.f + expf(-t1)),
                                    1.f / (1.f + expf(-t2)), 1.f / (1.f + expf(-t3)));
            }
        }
    }
}

// ---------------- edge scatter: acc[dst] += z[src] (one warp per edge, float4 atomics) ----------------
__global__ void scatter_kernel(const int* __restrict__ src, const int* __restrict__ dst,
                               const float4* __restrict__ z4, float4* __restrict__ acc4, int E) {
    int gtid = blockIdx.x * blockDim.x + threadIdx.x;
    int warp = gtid >> 5;
    int lane = gtid & 31;
    if (warp >= E) return;
    int s = __ldg(&src[warp]);
    int d = __ldg(&dst[warp]);
    float4 v = __ldg(&z4[(size_t)s * 32 + lane]);
    atomicAdd(&acc4[(size_t)d * 32 + lane], v);   // sm_90+: native float4 RED
}

// ---------------- epilogue: h = post(dinv[row]*acc + b), post = ReLU (+ LayerNorm) ----------------
template <int DO_LN>
__global__ void epilogue_kernel(const float* __restrict__ acc, const float* __restrict__ dinv,
                                const float* __restrict__ b, const float* __restrict__ g,
                                const float* __restrict__ be, float* __restrict__ hout) {
    const int row = blockIdx.x;
    const int d = threadIdx.x;   // 128 threads
    float v = fmaf(dinv[row], acc[(size_t)row * 128 + d], b[d]);
    v = fmaxf(v, 0.f);
    if (DO_LN) {
        __shared__ float red[4];
        float s = v;
#pragma unroll
        for (int o = 16; o > 0; o >>= 1) s += __shfl_xor_sync(0xffffffffu, s, o);
        if ((d & 31) == 0) red[d >> 5] = s;
        __syncthreads();
        float mu = (red[0] + red[1] + red[2] + red[3]) * (1.f / 128.f);
        __syncthreads();
        float x = v - mu;
        float s2 = x * x;
#pragma unroll
        for (int o = 16; o > 0; o >>= 1) s2 += __shfl_xor_sync(0xffffffffu, s2, o);
        if ((d & 31) == 0) red[d >> 5] = s2;
        __syncthreads();
        float var = (red[0] + red[1] + red[2] + red[3]) * (1.f / 128.f);
        v = fmaf(g[d] * x, rsqrtf(var + LN_EPS), be[d]);
    }
    hout[(size_t)row * 128 + d] = v;
}

// ---------------- launch ----------------
extern "C" void kernel_launch(void* const* d_in, const int* in_sizes, int n_in,
                              void* d_out, int out_size) {
    const float* x   = (const float*)d_in[0];
    const int*   ei  = (const int*)  d_in[1];
    const float* W1  = (const float*)d_in[2];
    const float* b1  = (const float*)d_in[3];
    const float* W2  = (const float*)d_in[4];
    const float* b2  = (const float*)d_in[5];
    const float* W3  = (const float*)d_in[6];
    const float* b3  = (const float*)d_in[7];
    const float* g1  = (const float*)d_in[8];
    const float* be1 = (const float*)d_in[9];
    const float* g2  = (const float*)d_in[10];
    const float* be2 = (const float*)d_in[11];
    const float* Wp1 = (const float*)d_in[12];
    const float* bp1 = (const float*)d_in[13];
    const float* Wp2 = (const float*)d_in[14];
    const float* bp2 = (const float*)d_in[15];
    float* out = (float*)d_out;

    const int n = in_sizes[0] / DIM;          // 100000
    const int E = in_sizes[1] / 2;            // 1600000
    const int* src = ei;
    const int* dst = ei + E;

    float *deg, *dinv, *bufA, *bufB, *bufC;
    cudaGetSymbolAddress((void**)&deg,  g_deg);
    cudaGetSymbolAddress((void**)&dinv, g_dinv);
    cudaGetSymbolAddress((void**)&bufA, g_bufA);
    cudaGetSymbolAddress((void**)&bufB, g_bufB);
    cudaGetSymbolAddress((void**)&bufC, g_bufC);

    const int SMEM128 = (128 * 68 + 128 * 128) * 4;  // 100352 B
    const int SMEM64  = (128 * 68 + 128 * 64)  * 4;  // 67584 B
    cudaFuncSetAttribute(gemm_kernel<128, 0>, cudaFuncAttributeMaxDynamicSharedMemorySize, SMEM128);
    cudaFuncSetAttribute(gemm_kernel<128, 1>, cudaFuncAttributeMaxDynamicSharedMemorySize, SMEM128);
    cudaFuncSetAttribute(gemm_kernel<64,  2>, cudaFuncAttributeMaxDynamicSharedMemorySize, SMEM64);

    const int gemm_grid = (n + 63) / 64;               // 1563
    const int scat_grid = (E * 32 + 255) / 256;

    // degree / dinv
    deg_init_kernel<<<(n + 255) / 256, 256>>>(deg, n);
    deg_count_kernel<<<(E + 255) / 256, 256>>>(dst, deg, E);
    dinv_kernel<<<(n + 255) / 256, 256>>>(deg, dinv, n);

    // ---- conv1: x -> bufC (ReLU + LN) ----
    gemm_kernel<128, 0><<<gemm_grid, 256, SMEM128>>>(x, W1, nullptr, dinv, bufA, bufB, n);
    scatter_kernel<<<scat_grid, 256>>>(src, dst, (const float4*)bufA, (float4*)bufB, E);
    epilogue_kernel<1><<<n, 128>>>(bufB, dinv, b1, g1, be1, bufC);

    // ---- conv2: bufC -> bufC (ReLU + LN) ----
    gemm_kernel<128, 0><<<gemm_grid, 256, SMEM128>>>(bufC, W2, nullptr, dinv, bufA, bufB, n);
    scatter_kernel<<<scat_grid, 256>>>(src, dst, (const float4*)bufA, (float4*)bufB, E);
    epilogue_kernel<1><<<n, 128>>>(bufB, dinv, b2, g2, be2, bufC);

    // ---- conv3: bufC -> bufC (ReLU only) ----
    gemm_kernel<128, 0><<<gemm_grid, 256, SMEM128>>>(bufC, W3, nullptr, dinv, bufA, bufB, n);
    scatter_kernel<<<scat_grid, 256>>>(src, dst, (const float4*)bufA, (float4*)bufB, E);
    epilogue_kernel<0><<<n, 128>>>(bufB, dinv, b3, nullptr, nullptr, bufC);

    // ---- heads: Wp1 (+bias), Wp2 (+bias, sigmoid) -> out ----
    gemm_kernel<128, 1><<<gemm_grid, 256, SMEM128>>>(bufC, Wp1, bp1, nullptr, bufA, nullptr, n);
    gemm_kernel<64,  2><<<gemm_grid, 256, SMEM64 >>>(bufA, Wp2, bp2, nullptr, out,  nullptr, n);
}

// round 4
// speedup vs baseline: 4.5400x; 1.6481x over previous
#include <cuda_runtime.h>
#include <math.h>

#define NMAX 100000
#define EMAX 2000000
#define DIM 128
#define LN_EPS 1e-5f

typedef unsigned long long u64;

// ---------------- packed f32x2 helpers (sm_103a) ----------------
#define FMA_F32X2(d, a, b) \
    asm("fma.rn.f32x2 %0, %1, %2, %0;" : "+l"(d) : "l"(a), "l"(b))
#define PACK_F32X2(out, lo, hi) \
    asm("mov.b64 %0, {%1, %2};" : "=l"(out) : "f"(lo), "f"(hi))
#define UNPACK_F32X2(lo, hi, in) \
    asm("mov.b64 {%0, %1}, %2;" : "=f"(lo), "=f"(hi) : "l"(in))

// ---------------- static scratch ----------------
__device__ int   g_deg [NMAX];
__device__ int   g_off [NMAX + 1];
__device__ int   g_cur [NMAX];
__device__ int   g_srcs[EMAX];
__device__ float g_dinv[NMAX];
__device__ float g_bufA[(size_t)NMAX * DIM];   // z = (h @ W) * dinv[row]
__device__ float g_bufC[(size_t)NMAX * DIM];   // layer activations

// ---------------- CSR build ----------------
__global__ void zero_deg_kernel(int* __restrict__ deg, int n) {
    int i = blockIdx.x * blockDim.x + threadIdx.x;
    if (i < n) deg[i] = 0;
}

__global__ void hist_kernel(const int* __restrict__ dst, int* __restrict__ deg, int E) {
    int e = blockIdx.x * blockDim.x + threadIdx.x;
    if (e < E) atomicAdd(&deg[dst[e]], 1);
}

// single block, 1024 threads: exclusive scan of deg -> off/cur, also dinv = rsqrt(deg+1)
__global__ __launch_bounds__(1024)
void scan_kernel(const int* __restrict__ deg, int* __restrict__ off, int* __restrict__ cur,
                 float* __restrict__ dinv, int n) {
    __shared__ int part[1024];
    const int tid = threadIdx.x;
    const int per = (n + 1023) / 1024;
    const int base = tid * per;
    int s = 0;
    for (int i = 0; i < per; i++) {
        int idx = base + i;
        if (idx < n) s += deg[idx];
    }
    part[tid] = s;
    __syncthreads();
    // Hillis-Steele inclusive scan
    for (int o = 1; o < 1024; o <<= 1) {
        int v = (tid >= o) ? part[tid - o] : 0;
        __syncthreads();
        part[tid] += v;
        __syncthreads();
    }
    int run = (tid == 0) ? 0 : part[tid - 1];   // exclusive prefix
    for (int i = 0; i < per; i++) {
        int idx = base + i;
        if (idx < n) {
            off[idx] = run;
            cur[idx] = run;
            dinv[idx] = rsqrtf((float)deg[idx] + 1.0f);
            run += deg[idx];
            if (idx == n - 1) off[n] = run;
        }
    }
}

__global__ void bucket_kernel(const int* __restrict__ src, const int* __restrict__ dst,
                              int* __restrict__ cur, int* __restrict__ sorted, int E) {
    int e = blockIdx.x * blockDim.x + threadIdx.x;
    if (e < E) {
        int p = atomicAdd(&cur[dst[e]], 1);
        sorted[p] = src[e];
    }
}

// ---------------- persistent GEMM: out = A[M,128] @ W[128,BN] ----------------
// 296 blocks, 256 threads; W staged to smem ONCE; loop over 64-row tiles.
// Thread (tr=tid>>4, cx=tid&15): rows r0=4*tr, cols {g*64 + 4*cx .. +3} per group g.
// Conflict-free: W LDS.128 lane stride = 16B; A LDS.128 broadcast per half-warp.
// MODE 0: v *= dinv[row]           MODE 1: v += bias   MODE 2: v = sigmoid(v + bias)
template <int BN, int MODE>
__global__ __launch_bounds__(256)
void gemm_kernel(const float* __restrict__ A, const float* __restrict__ W,
                 const float* __restrict__ bias, const float* __restrict__ dinv,
                 float* __restrict__ out1, int M, int ntiles) {
    constexpr int BM = 64;
    constexpr int NG = BN / 64;           // 64-col groups (2 or 1)
    constexpr int SAS = BM + 4;           // sAT stride: keeps 16B alignment, pads banks

    extern __shared__ float smem[];
    float* sW  = smem;                    // [128][BN]
    float* sAT = smem + 128 * BN;         // [128][SAS]

    const int tid = threadIdx.x;
    const int cx = tid & 15;
    const int tr = tid >> 4;
    const int r0 = tr * 4;

    // stage W once
    {
        const float4* Wv = (const float4*)W;
        float4* sWv = (float4*)sW;
        for (int i = tid; i < 128 * BN / 4; i += 256) sWv[i] = Wv[i];
    }

    float bv[NG][4];
    if (MODE != 0) {
#pragma unroll
        for (int g = 0; g < NG; g++)
#pragma unroll
            for (int j = 0; j < 4; j++) bv[g][j] = __ldg(&bias[g * 64 + cx * 4 + j]);
    }

    for (int tile = blockIdx.x; tile < ntiles; tile += gridDim.x) {
        const int rowbase = tile * BM;
        const int nrows = min(BM, M - rowbase);

        __syncthreads();   // previous iteration's readers done
        // load A tile (64 x 128) transposed into sAT[k][m]
        for (int i = tid; i < BM * 32; i += 256) {
            int r = i >> 5, c4 = i & 31;
            float4 v = make_float4(0.f, 0.f, 0.f, 0.f);
            if (r < nrows)
                v = ((const float4*)(A + (size_t)(rowbase + r) * 128))[c4];
            sAT[(4 * c4 + 0) * SAS + r] = v.x;
            sAT[(4 * c4 + 1) * SAS + r] = v.y;
            sAT[(4 * c4 + 2) * SAS + r] = v.z;
            sAT[(4 * c4 + 3) * SAS + r] = v.w;
        }
        __syncthreads();

        u64 acc[4][NG][2];
#pragma unroll
        for (int i = 0; i < 4; i++)
#pragma unroll
            for (int g = 0; g < NG; g++) { acc[i][g][0] = 0ULL; acc[i][g][1] = 0ULL; }

#pragma unroll 8
        for (int k = 0; k < 128; k++) {
            float4 a4 = *(const float4*)&sAT[k * SAS + r0];
            u64 aa[4];
            PACK_F32X2(aa[0], a4.x, a4.x);
            PACK_F32X2(aa[1], a4.y, a4.y);
            PACK_F32X2(aa[2], a4.z, a4.z);
            PACK_F32X2(aa[3], a4.w, a4.w);
#pragma unroll
            for (int g = 0; g < NG; g++) {
                const u64* w2 = (const u64*)&sW[k * BN + g * 64 + cx * 4];  // 16B aligned, lane stride 16B
                u64 w0 = w2[0], w1 = w2[1];
#pragma unroll
                for (int i = 0; i < 4; i++) {
                    FMA_F32X2(acc[i][g][0], aa[i], w0);
                    FMA_F32X2(acc[i][g][1], aa[i], w1);
                }
            }
        }

#pragma unroll
        for (int i = 0; i < 4; i++) {
            const int grow = rowbase + r0 + i;
            if (grow >= M) break;
            const float s = (MODE == 0) ? dinv[grow] : 0.f;
#pragma unroll
            for (int g = 0; g < NG; g++) {
                float v0, v1, v2, v3;
                UNPACK_F32X2(v0, v1, acc[i][g][0]);
                UNPACK_F32X2(v2, v3, acc[i][g][1]);
                float4* o = (float4*)(out1 + (size_t)grow * BN + g * 64 + cx * 4);
                if (MODE == 0) {
                    *o = make_float4(v0 * s, v1 * s, v2 * s, v3 * s);
                } else if (MODE == 1) {
                    *o = make_float4(v0 + bv[g][0], v1 + bv[g][1], v2 + bv[g][2], v3 + bv[g][3]);
                } else {
                    float t0 = v0 + bv[g][0], t1 = v1 + bv[g][1];
                    float t2 = v2 + bv[g][2], t3 = v3 + bv[g][3];
                    *o = make_float4(1.f / (1.f + expf(-t0)), 1.f / (1.f + expf(-t1)),
                                     1.f / (1.f + expf(-t2)), 1.f / (1.f + expf(-t3)));
                }
            }
        }
    }
}

// ---------------- fused CSR aggregate + self-loop + dinv + bias + ReLU (+LN) ----------------
// one warp per node; lane owns float4 (4 of 128 features)
template <int DO_LN>
__global__ __launch_bounds__(256)
void aggregate_kernel(const float4* __restrict__ z, const int* __restrict__ off,
                      const int* __restrict__ srcs, const float* __restrict__ dinv,
                      const float* __restrict__ b, const float* __restrict__ g,
                      const float* __restrict__ be, float4* __restrict__ out, int n) {
    const int warp = (blockIdx.x * blockDim.x + threadIdx.x) >> 5;
    const int lane = threadIdx.x & 31;
    if (warp >= n) return;

    const int s0 = __ldg(&off[warp]);
    const int s1 = __ldg(&off[warp + 1]);

    float4 acc = __ldg(&z[(size_t)warp * 32 + lane]);   // self loop (z already has dinv[src] factor)
    for (int base = s0; base < s1; base += 32) {
        const int cnt = min(32, s1 - base);
        int mys = (base + lane < s1) ? __ldg(&srcs[base + lane]) : 0;
#pragma unroll 4
        for (int j = 0; j < cnt; j++) {
            int sn = __shfl_sync(0xffffffffu, mys, j);
            float4 v = __ldg(&z[(size_t)sn * 32 + lane]);
            acc.x += v.x; acc.y += v.y; acc.z += v.z; acc.w += v.w;
        }
    }

    const float dv = __ldg(&dinv[warp]);
    const float4 bb = ((const float4*)b)[lane];
    float4 v = make_float4(fmaxf(fmaf(dv, acc.x, bb.x), 0.f),
                           fmaxf(fmaf(dv, acc.y, bb.y), 0.f),
                           fmaxf(fmaf(dv, acc.z, bb.z), 0.f),
                           fmaxf(fmaf(dv, acc.w, bb.w), 0.f));
    if (DO_LN) {
        float s = v.x + v.y + v.z + v.w;
#pragma unroll
        for (int o = 16; o > 0; o >>= 1) s += __shfl_xor_sync(0xffffffffu, s, o);
        const float mu = s * (1.f / 128.f);
        float4 xc = make_float4(v.x - mu, v.y - mu, v.z - mu, v.w - mu);
        float s2 = xc.x * xc.x + xc.y * xc.y + xc.z * xc.z + xc.w * xc.w;
#pragma unroll
        for (int o = 16; o > 0; o >>= 1) s2 += __shfl_xor_sync(0xffffffffu, s2, o);
        const float rs = rsqrtf(s2 * (1.f / 128.f) + LN_EPS);
        const float4 gg = ((const float4*)g)[lane];
        const float4 ee = ((const float4*)be)[lane];
        v = make_float4(fmaf(gg.x * xc.x, rs, ee.x), fmaf(gg.y * xc.y, rs, ee.y),
                        fmaf(gg.z * xc.z, rs, ee.z), fmaf(gg.w * xc.w, rs, ee.w));
    }
    out[(size_t)warp * 32 + lane] = v;
}

// ---------------- launch ----------------
extern "C" void kernel_launch(void* const* d_in, const int* in_sizes, int n_in,
                              void* d_out, int out_size) {
    const float* x   = (const float*)d_in[0];
    const int*   ei  = (const int*)  d_in[1];
    const float* W1  = (const float*)d_in[2];
    const float* b1  = (const float*)d_in[3];
    const float* W2  = (const float*)d_in[4];
    const float* b2  = (const float*)d_in[5];
    const float* W3  = (const float*)d_in[6];
    const float* b3  = (const float*)d_in[7];
    const float* g1  = (const float*)d_in[8];
    const float* be1 = (const float*)d_in[9];
    const float* g2  = (const float*)d_in[10];
    const float* be2 = (const float*)d_in[11];
    const float* Wp1 = (const float*)d_in[12];
    const float* bp1 = (const float*)d_in[13];
    const float* Wp2 = (const float*)d_in[14];
    const float* bp2 = (const float*)d_in[15];
    float* out = (float*)d_out;

    const int n = in_sizes[0] / DIM;          // 100000
    const int E = in_sizes[1] / 2;            // 1600000
    const int* src = ei;
    const int* dst = ei + E;

    int *deg, *off, *cur, *srcs;
    float *dinv, *bufA, *bufC;
    cudaGetSymbolAddress((void**)&deg,  g_deg);
    cudaGetSymbolAddress((void**)&off,  g_off);
    cudaGetSymbolAddress((void**)&cur,  g_cur);
    cudaGetSymbolAddress((void**)&srcs, g_srcs);
    cudaGetSymbolAddress((void**)&dinv, g_dinv);
    cudaGetSymbolAddress((void**)&bufA, g_bufA);
    cudaGetSymbolAddress((void**)&bufC, g_bufC);

    const int SMEM128 = (128 * 128 + 128 * 68) * 4;  // 100352 B
    const int SMEM64  = (128 * 64  + 128 * 68) * 4;  // 67584 B
    cudaFuncSetAttribute(gemm_kernel<128, 0>, cudaFuncAttributeMaxDynamicSharedMemorySize, SMEM128);
    cudaFuncSetAttribute(gemm_kernel<128, 1>, cudaFuncAttributeMaxDynamicSharedMemorySize, SMEM128);
    cudaFuncSetAttribute(gemm_kernel<64,  2>, cudaFuncAttributeMaxDynamicSharedMemorySize, SMEM64);

    const int ntiles = (n + 63) / 64;                // 1563
    const int GEMM_GRID = 296;                       // 2 blocks/SM
    const int agg_grid = (n * 32 + 255) / 256;       // 1 warp per node

    // ---- CSR build (reused by all 3 convs) ----
    zero_deg_kernel<<<(n + 255) / 256, 256>>>(deg, n);
    hist_kernel<<<(E + 255) / 256, 256>>>(dst, deg, E);
    scan_kernel<<<1, 1024>>>(deg, off, cur, dinv, n);
    bucket_kernel<<<(E + 255) / 256, 256>>>(src, dst, cur, srcs, E);

    // ---- conv1 ----
    gemm_kernel<128, 0><<<GEMM_GRID, 256, SMEM128>>>(x, W1, nullptr, dinv, bufA, n, ntiles);
    aggregate_kernel<1><<<agg_grid, 256>>>((const float4*)bufA, off, srcs, dinv, b1, g1, be1, (float4*)bufC, n);

    // ---- conv2 ----
    gemm_kernel<128, 0><<<GEMM_GRID, 256, SMEM128>>>(bufC, W2, nullptr, dinv, bufA, n, ntiles);
    aggregate_kernel<1><<<agg_grid, 256>>>((const float4*)bufA, off, srcs, dinv, b2, g2, be2, (float4*)bufC, n);

    // ---- conv3 (no LN) ----
    gemm_kernel<128, 0><<<GEMM_GRID, 256, SMEM128>>>(bufC, W3, nullptr, dinv, bufA, n, ntiles);
    aggregate_kernel<0><<<agg_grid, 256>>>((const float4*)bufA, off, srcs, dinv, b3, nullptr, nullptr, (float4*)bufC, n);

    // ---- heads ----
    gemm_kernel<128, 1><<<GEMM_GRID, 256, SMEM128>>>(bufC, Wp1, bp1, nullptr, bufA, n, ntiles);
    gemm_kernel<64,  2><<<GEMM_GRID, 256, SMEM64 >>>(bufA, Wp2, bp2, nullptr, out,  n, ntiles);
}